// round 3
// baseline (speedup 1.0000x reference)
#include <cuda_runtime.h>
#include <cstdint>

#define TOPK      2000
#define NMS_THR   0.5f
#define MAXN      200000
#define MAXG      128
#define HBINS     65536
#define CAP       8192
#define CBLK      32          // ceil(TOPK/64)
#define BM        256         // proposals per block in main kernel

// ---------------- scratch (no allocation allowed) ----------------
__device__ float               g_score[MAXN];
__device__ float4              g_boxper[MAXN];
__device__ __align__(16) int   g_hist[HBINS];     // zero at load; re-zeroed by sort_kernel
__device__ int                 g_candcount;       // zero at load; re-zeroed by sort_kernel
__device__ int                 g_binB;
__device__ unsigned long long  g_cand[CAP];
__device__ float4              g_topboxes[TOPK];
__device__ unsigned long long  g_mask[TOPK * CBLK];

// ---------------- kernel A: fused per-proposal ----------------
__global__ void __launch_bounds__(BM) main_kernel(
        const float4* __restrict__ prop,
        const float4* __restrict__ btp,   // (N*C) float4
        const float*  __restrict__ cls,
        const float4* __restrict__ gt,
        const int* __restrict__ ihp,
        const int* __restrict__ iwp,
        float4* __restrict__ out,         // full output, rows (TOPK+n)
        int N, int C, int G)
{
    __shared__ float4 sgtb[MAXG];
    __shared__ float  sga[MAXG];
    extern __shared__ float scls[];       // BM*21 (stride 21 -> conflict-free)

    int tid = threadIdx.x;
    int n0  = blockIdx.x * BM;

    int vi = ihp[0];
    float H = (vi > 0 && vi < 1000000) ? (float)vi : __int_as_float(vi);
    vi = iwp[0];
    float W = (vi > 0 && vi < 1000000) ? (float)vi : __int_as_float(vi);

    for (int i = tid; i < G; i += BM) {
        float4 g = gt[i];
        sgtb[i] = g;
        sga[i]  = (g.z - g.x) * (g.w - g.y);
    }
    // stage cls rows (coalesced global reads), constant-divide path for C==21
    {
        int rows = min(BM, N - n0);
        const float* cbase = cls + (size_t)n0 * C;
        if (C == 21) {
            int total = rows * 21;
            for (int idx = tid; idx < total; idx += BM) {
                int r = idx / 21;              // compile-time const division
                scls[r * 21 + (idx - r * 21)] = cbase[idx];
            }
        } else {
            int total = rows * C;
            for (int idx = tid; idx < total; idx += BM) {
                int r = idx / C;
                scls[r * 21 + (idx - r * C)] = cbase[idx];
            }
        }
    }
    __syncthreads();

    int n = n0 + tid;
    if (n >= N) return;

    float4 p = prop[n];
    float pw = p.z - p.x, ph = p.w - p.y;
    float pcx = p.x + 0.5f * pw, pcy = p.y + 0.5f * ph;
    float parea = pw * ph;

    // softmax score + fg argmax (from shared)
    const float* cr = scls + tid * 21;
    float m = cr[0], bl = -1e30f; int bc = 1;
    #pragma unroll
    for (int c = 1; c < 21; c++) {
        float v = cr[c];
        m = fmaxf(m, v);
        if (v > bl) { bl = v; bc = c; }
    }
    float Z = 0.f;
    #pragma unroll
    for (int c = 0; c < 21; c++) Z += __expf(cr[c] - m);
    float score = __fdividef(__expf(bl - m), Z);

    // decode selected class box, clamp
    float4 t = btp[(size_t)n * C + bc];
    float dcx = t.x * pw + pcx;
    float dcy = t.y * ph + pcy;
    float dw  = __expf(t.z) * pw;
    float dh  = __expf(t.w) * ph;
    float4 box;
    box.x = fminf(fmaxf(dcx - 0.5f * dw, 0.f), W);
    box.y = fminf(fmaxf(dcy - 0.5f * dh, 0.f), H);
    box.z = fminf(fmaxf(dcx + 0.5f * dw, 0.f), W);
    box.w = fminf(fmaxf(dcy + 0.5f * dh, 0.f), H);

    g_boxper[n] = box;
    g_score[n]  = score;
    atomicAdd(&g_hist[__float_as_uint(score) >> 16], 1);

    // best-IoU gt match: argmax of inter/den via cross-multiply (no division)
    float bnum = -1.0f, bden = 1.0f; int bg = 0;
    #pragma unroll 4
    for (int g = 0; g < G; g++) {
        float4 gb = sgtb[g];               // LDS.128 broadcast
        float lx = fmaxf(gb.x, p.x);
        float ly = fmaxf(gb.y, p.y);
        float rx = fminf(gb.z, p.z);
        float ry = fminf(gb.w, p.w);
        float iw = fmaxf(rx - lx, 0.f), ihh = fmaxf(ry - ly, 0.f);
        float inter = iw * ihh;
        float den = sga[g] + parea - inter;
        if (inter * bden > bnum * den) { bnum = inter; bden = den; bg = g; }
    }
    float4 gb = sgtb[bg];
    float gw = gb.z - gb.x, gh = gb.w - gb.y;
    float gcx = gb.x + 0.5f * gw, gcy = gb.y + 0.5f * gh;
    float4 rt;
    rt.x = __fdividef(gcx - pcx, pw);
    rt.y = __fdividef(gcy - pcy, ph);
    rt.z = __logf(__fdividef(gw, pw));
    rt.w = __logf(__fdividef(gh, ph));
    out[TOPK + n] = rt;
}

// ---------------- kernel B: find histogram cutoff bin ----------------
// Coalesced chunk sums (warp per chunk) + block scan.
__global__ void findbin_kernel() {
    __shared__ int csum[1024];
    __shared__ int cscan[1024];
    int tid = threadIdx.x;
    int w = tid >> 5, lane = tid & 31;
    for (int c = w; c < 1024; c += 32) {
        int base = HBINS - (c + 1) * 64;          // chunk c = top-down chunk
        int s = g_hist[base + lane] + g_hist[base + 32 + lane];
        s = __reduce_add_sync(0xFFFFFFFFu, s);
        if (lane == 0) csum[c] = s;
    }
    __syncthreads();
    int v = csum[tid];
    cscan[tid] = v;
    __syncthreads();
    for (int off = 1; off < 1024; off <<= 1) {
        int add = (tid >= off) ? cscan[tid - off] : 0;
        __syncthreads();
        cscan[tid] += add;
        __syncthreads();
    }
    int incl = cscan[tid], excl = incl - v;
    if (excl < TOPK && incl >= TOPK) {            // unique thread
        int run = excl;
        int hi = HBINS - 64 * tid - 1;
        for (int b = hi; b > hi - 64; b--) {
            run += g_hist[b];
            if (run >= TOPK) { g_binB = b; break; }
        }
    }
}

// ---------------- kernel C: compact candidates ----------------
__global__ void compact_kernel(int N) {
    int n = blockIdx.x * blockDim.x + threadIdx.x;
    if (n >= N) return;
    unsigned bits = __float_as_uint(g_score[n]);
    if ((int)(bits >> 16) >= g_binB) {
        int pos = atomicAdd(&g_candcount, 1);
        if (pos < CAP)
            g_cand[pos] = ((unsigned long long)bits << 32) | (unsigned)(~n);
    }
}

// ---------------- kernel D: bitonic sort + gather + scratch re-zero -------
__global__ void sort_kernel() {
    extern __shared__ unsigned long long sk[];
    int M = g_candcount; if (M > CAP) M = CAP;
    int P = 2048;
    while (P < M) P <<= 1;
    for (int i = threadIdx.x; i < P; i += blockDim.x)
        sk[i] = (i < M) ? g_cand[i] : 0ULL;
    // re-zero scratch for the next replay (all readers of hist/candcount done)
    {
        int4 z = make_int4(0, 0, 0, 0);
        int4* hp = reinterpret_cast<int4*>(g_hist);
        for (int i = threadIdx.x; i < HBINS / 4; i += blockDim.x) hp[i] = z;
        if (threadIdx.x == 0) g_candcount = 0;
    }
    __syncthreads();
    for (int k = 2; k <= P; k <<= 1) {
        for (int j = k >> 1; j > 0; j >>= 1) {
            for (int i = threadIdx.x; i < P; i += blockDim.x) {
                int l = i ^ j;
                if (l > i) {
                    bool desc = ((i & k) == 0);
                    unsigned long long a = sk[i], b = sk[l];
                    if (desc ? (a < b) : (a > b)) { sk[i] = b; sk[l] = a; }
                }
            }
            __syncthreads();
        }
    }
    for (int i = threadIdx.x; i < TOPK; i += blockDim.x) {
        unsigned n = ~(unsigned)(sk[i] & 0xFFFFFFFFULL);
        g_topboxes[i] = g_boxper[n];
    }
}

// ---------------- kernel E: NMS suppression bitmask ----------------
__global__ void __launch_bounds__(256) nms_mask_kernel() {
    __shared__ float4 sb[64];
    int cb = blockIdx.x;
    int t = threadIdx.x;
    int col0 = cb * 64;
    if (t < 64 && col0 + t < TOPK) sb[t] = g_topboxes[col0 + t];
    __syncthreads();
    int row = blockIdx.y * 256 + t;
    if (row >= TOPK) return;
    float4 a = g_topboxes[row];
    float aarea = (a.z - a.x) * (a.w - a.y);
    unsigned long long bits = 0;
    int nj = min(64, TOPK - col0);
    for (int j = 0; j < nj; j++) {
        float4 b = sb[j];
        float lx = fmaxf(a.x, b.x), ly = fmaxf(a.y, b.y);
        float rx = fminf(a.z, b.z), ry = fminf(a.w, b.w);
        float iw = fmaxf(rx - lx, 0.f), ih = fmaxf(ry - ly, 0.f);
        float inter = iw * ih;
        float barea = (b.z - b.x) * (b.w - b.y);
        float iou = __fdividef(inter, aarea + barea - inter);
        if (iou > NMS_THR) bits |= (1ULL << j);   // NaN compares false
    }
    g_mask[row * CBLK + cb] = bits;
}

// ---------------- kernel F: greedy scan (short ALU chain) + final write ----
__global__ void __launch_bounds__(256) nms_final_kernel(float* __restrict__ out) {
    __shared__ unsigned long long skeep[CBLK];
    int tid = threadIdx.x;
    if (tid < 32) {
        const int t = tid;
        unsigned long long rem = 0;        // lane t: suppression for col block t
        unsigned long long cur_sup = 0;    // replicated: suppression of current 64-row block
        unsigned long long kw = 0;         // keep bits of current block (replicated)
        unsigned long long bit = 1;
        const int D = 8;
        unsigned long long buf[D];
        #pragma unroll
        for (int k = 0; k < D; k++) buf[k] = g_mask[k * CBLK + t];
        // m pipeline: m0 = mask word of row i at its own column block (replicated)
        unsigned long long m0 = __shfl_sync(0xFFFFFFFFu, buf[0], 0);
        unsigned long long m1 = __shfl_sync(0xFFFFFFFFu, buf[1], 0);
        for (int i = 0; i < TOPK; i++) {
            unsigned long long cur = buf[i & (D - 1)];
            // schedule m for row i+2 (mask data only - off the serial chain)
            unsigned long long m2 = 0;
            if (i + 2 < TOPK)
                m2 = __shfl_sync(0xFFFFFFFFu, buf[(i + 2) & (D - 1)], (i + 2) >> 6);
            if (i + D < TOPK) buf[i & (D - 1)] = g_mask[(i + D) * CBLK + t];

            bool keep = (cur_sup & bit) == 0ULL;   // serial chain: AND+SETP
            if (keep) { cur_sup |= m0; kw |= bit; }
            rem |= keep ? cur : 0ULL;              // off-chain per-lane accumulate

            if ((i & 63) == 63) {                  // block boundary
                if (t == 0) skeep[i >> 6] = kw;
                kw = 0; bit = 1;
                cur_sup = __shfl_sync(0xFFFFFFFFu, rem, (i + 1) >> 6);
            } else {
                bit <<= 1;
            }
            m0 = m1; m1 = m2;
        }
        if (t == 0) skeep[(TOPK - 1) >> 6] = kw;   // flush partial last block
    }
    __syncthreads();
    const float* tb = (const float*)g_topboxes;
    for (int idx = tid; idx < TOPK * 4; idx += 256) {
        int row = idx >> 2;
        float k = ((skeep[row >> 6] >> (row & 63)) & 1ULL) ? 1.0f : 0.0f;
        out[idx] = tb[idx] * k;
    }
}

// ---------------- launcher ----------------
extern "C" void kernel_launch(void* const* d_in, const int* in_sizes, int n_in,
                              void* d_out, int out_size)
{
    const float4* prop = (const float4*)d_in[0];
    const float4* btp  = (const float4*)d_in[1];
    const float*  cls  = (const float*)d_in[2];
    const float4* gt   = (const float4*)d_in[3];
    const int*    ih   = (const int*)d_in[4];
    const int*    iw   = (const int*)d_in[5];
    float*        out  = (float*)d_out;

    int N = in_sizes[0] / 4;
    int C = in_sizes[2] / N;
    int G = in_sizes[3] / 4;

    int smem_main = BM * 21 * (int)sizeof(float);
    main_kernel<<<(N + BM - 1) / BM, BM, smem_main>>>(
        prop, btp, cls, gt, ih, iw, (float4*)out, N, C, G);

    findbin_kernel<<<1, 1024>>>();
    compact_kernel<<<(N + 255) / 256, 256>>>(N);

    static int smem_set = 0;
    if (!smem_set) {
        cudaFuncSetAttribute(sort_kernel,
                             cudaFuncAttributeMaxDynamicSharedMemorySize,
                             CAP * (int)sizeof(unsigned long long));
        smem_set = 1;
    }
    sort_kernel<<<1, 1024, CAP * sizeof(unsigned long long)>>>();

    dim3 grid((TOPK + 63) / 64, (TOPK + 255) / 256);
    nms_mask_kernel<<<grid, 256>>>();
    nms_final_kernel<<<1, 256>>>(out);
}